// round 1
// baseline (speedup 1.0000x reference)
#include <cuda_runtime.h>
#include <math.h>

static constexpr int   NUM_MOVABLE = 1000000;
static constexpr int   NUM_NODES   = 1200000;
static constexpr int   NB          = 512;
static constexpr int   MAP_SIZE    = NB * NB;
static constexpr float BS          = 1.953125f;   // 1000/512, exact in fp32
static constexpr int   NBANK       = 64;

// Scratch (static __device__ — no allocation)
__device__ float  g_route[MAP_SIZE];
__device__ float  g_pin[MAP_SIZE];
__device__ float  g_inc[NUM_MOVABLE];
__device__ double g_acc[5][NBANK];   // 0:old_sum 1:inc_sum 2:route_excess 3:pin_excess 4:filler_sum
__device__ float  g_scalars[4];      // 0:adjust 1:scale 2:fcond 3:fratio

// ---------------------------------------------------------------- K0: clamp maps + zero accumulators
__global__ void k_prep(const float* __restrict__ route, const float* __restrict__ pin) {
    int i = blockIdx.x * blockDim.x + threadIdx.x;
    if (i < 5 * NBANK) ((double*)g_acc)[i] = 0.0;
    if (i < MAP_SIZE) {
        float u = route[i];
        float r = u * u * sqrtf(u);                 // u^2.5
        g_route[i] = fminf(fmaxf(r, 0.5f), 2.0f);
        float p = pin[i];
        g_pin[i]   = fminf(fmaxf(p, 0.4f), 2.5f);
    }
}

// ---------------------------------------------------------------- K1: per-node areas + reductions
__global__ void __launch_bounds__(256) k_area(const float* __restrict__ pos,
                                              const float* __restrict__ nsx,
                                              const float* __restrict__ nsy) {
    int i = blockIdx.x * blockDim.x + threadIdx.x;
    float v_old = 0.f, v_inc = 0.f, v_re = 0.f, v_pe = 0.f, v_f = 0.f;
    if (i < NUM_NODES) {
        float sx = nsx[i], sy = nsy[i];
        float a = sx * sy;
        if (i < NUM_MOVABLE) {
            float px = pos[i], py = pos[NUM_NODES + i];
            float xh = px + sx, yh = py + sy;
            // node size < bin size -> at most 2x2 bins; 3rd bin overlap is exactly 0
            int bx0 = (int)floorf(px / BS);
            int by0 = (int)floorf(py / BS);
            float blx0 = bx0 * BS, bly0 = by0 * BS;
            float ox0 = fmaxf(fminf(xh, blx0 + BS)       - fmaxf(px, blx0),      0.f);
            float ox1 = fmaxf(fminf(xh, blx0 + 2.f * BS) - fmaxf(px, blx0 + BS), 0.f);
            float oy0 = fmaxf(fminf(yh, bly0 + BS)       - fmaxf(py, bly0),      0.f);
            float oy1 = fmaxf(fminf(yh, bly0 + 2.f * BS) - fmaxf(py, bly0 + BS), 0.f);
            int bx1 = min(bx0 + 1, NB - 1);  // weight is 0 when clamped/out of range
            int by1 = min(by0 + 1, NB - 1);
            int i00 = bx0 * NB + by0, i01 = bx0 * NB + by1;
            int i10 = bx1 * NB + by0, i11 = bx1 * NB + by1;
            float w00 = ox0 * oy0, w01 = ox0 * oy1, w10 = ox1 * oy0, w11 = ox1 * oy1;
            float ro = w00 * __ldg(&g_route[i00]) + w01 * __ldg(&g_route[i01])
                     + w10 * __ldg(&g_route[i10]) + w11 * __ldg(&g_route[i11]);
            float po = w00 * __ldg(&g_pin[i00]) + w01 * __ldg(&g_pin[i01])
                     + w10 * __ldg(&g_pin[i10]) + w11 * __ldg(&g_pin[i11]);
            float ainc = fmaxf(fmaxf(ro, po) - a, 0.f);
            g_inc[i] = ainc;
            v_old = a;
            v_inc = ainc;
            v_re  = fmaxf(ro - a, 0.f);
            v_pe  = fmaxf(po - a, 0.f);
        } else {
            v_f = a;   // filler area
        }
    }
    // warp reduce all five
    #pragma unroll
    for (int off = 16; off; off >>= 1) {
        v_old += __shfl_down_sync(0xffffffffu, v_old, off);
        v_inc += __shfl_down_sync(0xffffffffu, v_inc, off);
        v_re  += __shfl_down_sync(0xffffffffu, v_re , off);
        v_pe  += __shfl_down_sync(0xffffffffu, v_pe , off);
        v_f   += __shfl_down_sync(0xffffffffu, v_f  , off);
    }
    __shared__ float sm[5][8];
    int w = threadIdx.x >> 5, l = threadIdx.x & 31;
    if (l == 0) { sm[0][w] = v_old; sm[1][w] = v_inc; sm[2][w] = v_re; sm[3][w] = v_pe; sm[4][w] = v_f; }
    __syncthreads();
    if (threadIdx.x == 0) {
        int bank = blockIdx.x & (NBANK - 1);
        #pragma unroll
        for (int j = 0; j < 5; j++) {
            float s = 0.f;
            #pragma unroll
            for (int k = 0; k < 8; k++) s += sm[j][k];
            atomicAdd(&g_acc[j][bank], (double)s);
        }
    }
}

// ---------------------------------------------------------------- K2: global decision scalars
__global__ void k_scalar() {
    double s[5];
    #pragma unroll
    for (int j = 0; j < 5; j++) {
        double t = 0.0;
        for (int k = 0; k < NBANK; k++) t += g_acc[j][k];
        s[j] = t;
    }
    float old_sum = (float)s[0], inc_sum = (float)s[1];
    float re = (float)s[2], pe = (float)s[3], fsum = (float)s[4];

    float budget    = fminf(0.1f * 500000.0f, 1000000.0f - old_sum);
    float raw_scale = budget / inc_sum;
    float scale     = fminf(fmaxf(raw_scale, 0.f), 1.f);
    float inc_eff   = (raw_scale <= 0.f) ? 0.f : inc_sum * scale;
    float new_sum   = old_sum + inc_eff;
    float area_ratio = inc_eff / old_sum;
    bool route_flag = (re / old_sum) > 0.01f;
    bool pin_flag   = (pe / old_sum) > 0.05f;
    bool adjust = (area_ratio > 0.01f) && (route_flag || pin_flag);
    bool fcond  = adjust && (new_sum + fsum > 1000000.0f);
    float fratio = sqrtf(fmaxf(1000000.0f - new_sum, 0.f) / fsum);

    g_scalars[0] = adjust ? 1.f : 0.f;
    g_scalars[1] = scale;
    g_scalars[2] = fcond ? 1.f : 0.f;
    g_scalars[3] = fratio;
}

// ---------------------------------------------------------------- K3: apply + write outputs
__global__ void __launch_bounds__(256) k_write(const float* __restrict__ pos,
                                               const float* __restrict__ nsx,
                                               const float* __restrict__ nsy,
                                               float* __restrict__ out) {
    int i = blockIdx.x * blockDim.x + threadIdx.x;
    if (i >= NUM_NODES) return;
    float sx = nsx[i], sy = nsy[i];
    float px = pos[i], py = pos[NUM_NODES + i];
    float nx = sx, ny = sy, qx = px, qy = py;
    if (i < NUM_MOVABLE) {
        if (g_scalars[0] != 0.f) {
            float a  = sx * sy;
            float na = a + g_inc[i] * g_scalars[1];
            float mr = sqrtf(na / a);
            nx = sx * mr; ny = sy * mr;
            qx = px + 0.5f * (sx - nx);
            qy = py + 0.5f * (sy - ny);
        }
    } else {
        if (g_scalars[2] != 0.f) {
            float fr = g_scalars[3];
            nx = sx * fr; ny = sy * fr;
            qx = px + 0.5f * (sx - nx);
            qy = py + 0.5f * (sy - ny);
        }
    }
    out[i]                 = qx;   // new px (movable then filler = node order)
    out[NUM_NODES + i]     = qy;   // new py
    out[2 * NUM_NODES + i] = nx;   // new node_size_x
    out[3 * NUM_NODES + i] = ny;   // new node_size_y
}

// ----------------------------------------------------------------
extern "C" void kernel_launch(void* const* d_in, const int* in_sizes, int n_in,
                              void* d_out, int out_size) {
    const float* pos   = (const float*)d_in[0];
    const float* nsx   = (const float*)d_in[1];
    const float* nsy   = (const float*)d_in[2];
    const float* route = (const float*)d_in[6];
    const float* pin   = (const float*)d_in[7];
    float* out = (float*)d_out;

    k_prep  <<<(MAP_SIZE  + 255) / 256, 256>>>(route, pin);
    k_area  <<<(NUM_NODES + 255) / 256, 256>>>(pos, nsx, nsy);
    k_scalar<<<1, 1>>>();
    k_write <<<(NUM_NODES + 255) / 256, 256>>>(pos, nsx, nsy, out);
}

// round 2
// speedup vs baseline: 1.5882x; 1.5882x over previous
#include <cuda_runtime.h>
#include <math.h>

static constexpr int   NUM_MOVABLE = 1000000;
static constexpr int   NUM_NODES   = 1200000;
static constexpr int   NQ          = NUM_NODES / 4;      // 300000 quads
static constexpr int   NB          = 512;
static constexpr int   MAP_SIZE    = NB * NB;
static constexpr float BS          = 1.953125f;          // 1000/512, exact in fp32
static constexpr int   NBANK       = 64;

// Scratch (static __device__ — no allocation)
__device__ float2 g_maps[MAP_SIZE];          // .x = route clamped, .y = pin clamped
__device__ float  g_inc[NUM_MOVABLE];
__device__ double g_acc[5][NBANK];           // 0:old 1:inc 2:route_ex 3:pin_ex 4:filler

// ---------------------------------------------------------------- K0: clamp+interleave maps, zero acc
__global__ void k_prep(const float* __restrict__ route, const float* __restrict__ pin) {
    int i = blockIdx.x * blockDim.x + threadIdx.x;
    if (i < 5 * NBANK) ((double*)g_acc)[i] = 0.0;
    if (i < MAP_SIZE) {
        float u = route[i];
        float r = u * u * sqrtf(u);                       // u^2.5
        float p = pin[i];
        g_maps[i] = make_float2(fminf(fmaxf(r, 0.5f), 2.0f),
                                fminf(fmaxf(p, 0.4f), 2.5f));
    }
}

// ---------------------------------------------------------------- K1: per-node areas + banked reductions
__global__ void __launch_bounds__(256) k_area(const float4* __restrict__ posx,
                                              const float4* __restrict__ posy,
                                              const float4* __restrict__ nsx,
                                              const float4* __restrict__ nsy) {
    int q = blockIdx.x * 256 + threadIdx.x;
    float v_old = 0.f, v_inc = 0.f, v_re = 0.f, v_pe = 0.f, v_f = 0.f;
    if (q < NQ) {
        float4 sx4 = nsx[q], sy4 = nsy[q];
        float sxA[4], syA[4];
        *(float4*)sxA = sx4; *(float4*)syA = sy4;
        if (q * 4 < NUM_MOVABLE) {           // quad fully movable (1M % 4 == 0)
            float4 px4 = posx[q], py4 = posy[q];
            float pxA[4], pyA[4], incA[4];
            *(float4*)pxA = px4; *(float4*)pyA = py4;
            #pragma unroll
            for (int j = 0; j < 4; j++) {
                float sx = sxA[j], sy = syA[j];
                float px = pxA[j], py = pyA[j];
                float a  = sx * sy;
                float xh = px + sx, yh = py + sy;
                int bx0 = (int)floorf(px / BS);
                int by0 = (int)floorf(py / BS);
                float blx0 = bx0 * BS, bly0 = by0 * BS;
                // node < bin size -> at most 2x2 bins; 3rd overlap exactly 0
                float ox0 = fmaxf(fminf(xh, blx0 + BS)       - fmaxf(px, blx0),      0.f);
                float ox1 = fmaxf(fminf(xh, blx0 + 2.f * BS) - fmaxf(px, blx0 + BS), 0.f);
                float oy0 = fmaxf(fminf(yh, bly0 + BS)       - fmaxf(py, bly0),      0.f);
                float oy1 = fmaxf(fminf(yh, bly0 + 2.f * BS) - fmaxf(py, bly0 + BS), 0.f);
                int bx1 = min(bx0 + 1, NB - 1);
                int by1 = min(by0 + 1, NB - 1);
                float2 m00 = __ldg(&g_maps[bx0 * NB + by0]);
                float2 m01 = __ldg(&g_maps[bx0 * NB + by1]);
                float2 m10 = __ldg(&g_maps[bx1 * NB + by0]);
                float2 m11 = __ldg(&g_maps[bx1 * NB + by1]);
                float w00 = ox0 * oy0, w01 = ox0 * oy1, w10 = ox1 * oy0, w11 = ox1 * oy1;
                float ro = w00 * m00.x + w01 * m01.x + w10 * m10.x + w11 * m11.x;
                float po = w00 * m00.y + w01 * m01.y + w10 * m10.y + w11 * m11.y;
                float ainc = fmaxf(fmaxf(ro, po) - a, 0.f);
                incA[j] = ainc;
                v_old += a;
                v_inc += ainc;
                v_re  += fmaxf(ro - a, 0.f);
                v_pe  += fmaxf(po - a, 0.f);
            }
            ((float4*)g_inc)[q] = *(const float4*)incA;
        } else {                              // quad fully filler
            #pragma unroll
            for (int j = 0; j < 4; j++) v_f += sxA[j] * syA[j];
        }
    }
    // warp reduce all five
    #pragma unroll
    for (int off = 16; off; off >>= 1) {
        v_old += __shfl_down_sync(0xffffffffu, v_old, off);
        v_inc += __shfl_down_sync(0xffffffffu, v_inc, off);
        v_re  += __shfl_down_sync(0xffffffffu, v_re , off);
        v_pe  += __shfl_down_sync(0xffffffffu, v_pe , off);
        v_f   += __shfl_down_sync(0xffffffffu, v_f  , off);
    }
    __shared__ float sm[5][8];
    int w = threadIdx.x >> 5, l = threadIdx.x & 31;
    if (l == 0) { sm[0][w] = v_old; sm[1][w] = v_inc; sm[2][w] = v_re; sm[3][w] = v_pe; sm[4][w] = v_f; }
    __syncthreads();
    if (threadIdx.x == 0) {
        int bank = blockIdx.x & (NBANK - 1);
        #pragma unroll
        for (int j = 0; j < 5; j++) {
            float s = 0.f;
            #pragma unroll
            for (int k = 0; k < 8; k++) s += sm[j][k];
            atomicAdd(&g_acc[j][bank], (double)s);
        }
    }
}

// ---------------------------------------------------------------- K2: scalars (per-block) + apply + write
__global__ void __launch_bounds__(256) k_write(const float4* __restrict__ posx,
                                               const float4* __restrict__ posy,
                                               const float4* __restrict__ nsx,
                                               const float4* __restrict__ nsy,
                                               float4* __restrict__ out) {
    __shared__ float s_sc[4];     // 0:adjust 1:scale 2:fcond 3:fratio
    if (threadIdx.x < 32) {
        int l = threadIdx.x;
        double t0 = g_acc[0][l] + g_acc[0][l + 32];
        double t1 = g_acc[1][l] + g_acc[1][l + 32];
        double t2 = g_acc[2][l] + g_acc[2][l + 32];
        double t3 = g_acc[3][l] + g_acc[3][l + 32];
        double t4 = g_acc[4][l] + g_acc[4][l + 32];
        #pragma unroll
        for (int off = 16; off; off >>= 1) {
            t0 += __shfl_down_sync(0xffffffffu, t0, off);
            t1 += __shfl_down_sync(0xffffffffu, t1, off);
            t2 += __shfl_down_sync(0xffffffffu, t2, off);
            t3 += __shfl_down_sync(0xffffffffu, t3, off);
            t4 += __shfl_down_sync(0xffffffffu, t4, off);
        }
        if (l == 0) {
            float old_sum = (float)t0, inc_sum = (float)t1;
            float re = (float)t2, pe = (float)t3, fsum = (float)t4;
            float budget    = fminf(0.1f * 500000.0f, 1000000.0f - old_sum);
            float raw_scale = budget / inc_sum;
            float scale     = fminf(fmaxf(raw_scale, 0.f), 1.f);
            float inc_eff   = (raw_scale <= 0.f) ? 0.f : inc_sum * scale;
            float new_sum   = old_sum + inc_eff;
            bool route_flag = (re / old_sum) > 0.01f;
            bool pin_flag   = (pe / old_sum) > 0.05f;
            bool adjust = ((inc_eff / old_sum) > 0.01f) && (route_flag || pin_flag);
            bool fcond  = adjust && (new_sum + fsum > 1000000.0f);
            s_sc[0] = adjust ? 1.f : 0.f;
            s_sc[1] = scale;
            s_sc[2] = fcond ? 1.f : 0.f;
            s_sc[3] = sqrtf(fmaxf(1000000.0f - new_sum, 0.f) / fsum);
        }
    }
    __syncthreads();

    int q = blockIdx.x * 256 + threadIdx.x;
    if (q >= NQ) return;
    float adjust = s_sc[0], scale = s_sc[1], fcond = s_sc[2], fratio = s_sc[3];

    float4 sx4 = nsx[q], sy4 = nsy[q], px4 = posx[q], py4 = posy[q];
    float sxA[4], syA[4], pxA[4], pyA[4];
    *(float4*)sxA = sx4; *(float4*)syA = sy4;
    *(float4*)pxA = px4; *(float4*)pyA = py4;
    float nxA[4], nyA[4], qxA[4], qyA[4];

    if (q * 4 < NUM_MOVABLE) {
        float incA[4];
        *(float4*)incA = ((const float4*)g_inc)[q];
        #pragma unroll
        for (int j = 0; j < 4; j++) {
            float sx = sxA[j], sy = syA[j];
            float nx = sx, ny = sy, qx = pxA[j], qy = pyA[j];
            if (adjust != 0.f) {
                float a  = sx * sy;
                float na = a + incA[j] * scale;
                float mr = sqrtf(na / a);
                nx = sx * mr; ny = sy * mr;
                qx = pxA[j] + 0.5f * (sx - nx);
                qy = pyA[j] + 0.5f * (sy - ny);
            }
            nxA[j] = nx; nyA[j] = ny; qxA[j] = qx; qyA[j] = qy;
        }
    } else {
        #pragma unroll
        for (int j = 0; j < 4; j++) {
            float sx = sxA[j], sy = syA[j];
            float nx = sx, ny = sy, qx = pxA[j], qy = pyA[j];
            if (fcond != 0.f) {
                nx = sx * fratio; ny = sy * fratio;
                qx = pxA[j] + 0.5f * (sx - nx);
                qy = pyA[j] + 0.5f * (sy - ny);
            }
            nxA[j] = nx; nyA[j] = ny; qxA[j] = qx; qyA[j] = qy;
        }
    }
    out[q]          = *(const float4*)qxA;   // new pos x
    out[NQ + q]     = *(const float4*)qyA;   // new pos y
    out[2 * NQ + q] = *(const float4*)nxA;   // new node_size_x
    out[3 * NQ + q] = *(const float4*)nyA;   // new node_size_y
}

// ----------------------------------------------------------------
extern "C" void kernel_launch(void* const* d_in, const int* in_sizes, int n_in,
                              void* d_out, int out_size) {
    const float* pos   = (const float*)d_in[0];
    const float* nsx   = (const float*)d_in[1];
    const float* nsy   = (const float*)d_in[2];
    const float* route = (const float*)d_in[6];
    const float* pin   = (const float*)d_in[7];
    float* out = (float*)d_out;

    const float4* posx4 = (const float4*)pos;
    const float4* posy4 = (const float4*)(pos + NUM_NODES);
    const float4* nsx4  = (const float4*)nsx;
    const float4* nsy4  = (const float4*)nsy;

    k_prep <<<(MAP_SIZE + 255) / 256, 256>>>(route, pin);
    k_area <<<(NQ + 255) / 256, 256>>>(posx4, posy4, nsx4, nsy4);
    k_write<<<(NQ + 255) / 256, 256>>>(posx4, posy4, nsx4, nsy4, (float4*)out);
}

// round 4
// speedup vs baseline: 1.6895x; 1.0638x over previous
#include <cuda_runtime.h>
#include <math.h>

static constexpr int   NUM_MOVABLE = 1000000;
static constexpr int   NUM_NODES   = 1200000;
static constexpr int   NQ          = NUM_NODES / 4;      // 300000 quads
static constexpr int   NQ_MOV      = NUM_MOVABLE / 4;    // 250000 movable quads
static constexpr int   NB          = 512;
static constexpr int   MAP_SIZE    = NB * NB;
static constexpr float BS          = 1.953125f;          // 1000/512, exact fp32
static constexpr int   NBANK       = 64;
static constexpr int   NBLK        = 592;                // 148 SMs x 4 (co-resident)
static constexpr int   NTHR        = 256;
static constexpr int   NT          = NBLK * NTHR;        // 151552 threads

// Scratch (static __device__ — no allocation)
__device__ float2   g_maps[MAP_SIZE];        // .x route clamped, .y pin clamped
__device__ double   g_acc[5][NBANK];         // 0:old 1:inc 2:route_ex 3:pin_ex 4:filler
__device__ unsigned g_count = 0;             // barrier arrive counter (self-resetting)
__device__ unsigned g_sense = 0;             // barrier sense (flips 1 then back to 0)

// Sense-reversing grid barrier. Used exactly twice per launch with targets 1,0
// so device state returns to its initial value -> replay-deterministic.
__device__ __forceinline__ void grid_bar(unsigned target) {
    __syncthreads();
    if (threadIdx.x == 0) {
        __threadfence();
        if (atomicAdd(&g_count, 1u) == (unsigned)(NBLK - 1)) {
            g_count = 0u;
            __threadfence();
            atomicExch(&g_sense, target);
        } else {
            while (atomicAdd(&g_sense, 0u) != target) __nanosleep(64);
            __threadfence();
        }
    }
    __syncthreads();
}

__global__ void __launch_bounds__(NTHR, 4)
k_fused(const float4* __restrict__ posx, const float4* __restrict__ posy,
        const float4* __restrict__ nsx,  const float4* __restrict__ nsy,
        const float4* __restrict__ route4, const float4* __restrict__ pin4,
        float4* __restrict__ out) {
    const int tid = blockIdx.x * NTHR + threadIdx.x;

    // ---------------- Phase 0: clamp+interleave maps, zero accumulators ----
    if (tid < MAP_SIZE / 4) {
        float4 r4 = route4[tid], p4 = pin4[tid];
        float rA[4], pA[4];
        *(float4*)rA = r4; *(float4*)pA = p4;
        float2 m[4];
        #pragma unroll
        for (int j = 0; j < 4; j++) {
            float u = rA[j];
            float r = u * u * sqrtf(u);                    // u^2.5
            m[j] = make_float2(fminf(fmaxf(r, 0.5f), 2.0f),
                               fminf(fmaxf(pA[j], 0.4f), 2.5f));
        }
        float4* dst = (float4*)g_maps + 2 * tid;
        dst[0] = *(const float4*)&m[0];
        dst[1] = *(const float4*)&m[2];
    } else if (tid < MAP_SIZE / 4 + 5 * NBANK) {
        ((double*)g_acc)[tid - MAP_SIZE / 4] = 0.0;
    }

    grid_bar(1u);   // maps + zeroed accumulators visible grid-wide

    // ---------------- Phase 1: per-node areas + banked reductions ----------
    float inc[2][4];                                       // lives across barrier
    float v_old = 0.f, v_inc = 0.f, v_re = 0.f, v_pe = 0.f, v_f = 0.f;
    #pragma unroll
    for (int t = 0; t < 2; t++) {
        int q = tid + t * NT;
        if (q >= NQ) break;
        float4 sx4 = nsx[q], sy4 = nsy[q];
        float sxA[4], syA[4];
        *(float4*)sxA = sx4; *(float4*)syA = sy4;
        if (q < NQ_MOV) {
            float4 px4 = posx[q], py4 = posy[q];
            float pxA[4], pyA[4];
            *(float4*)pxA = px4; *(float4*)pyA = py4;
            #pragma unroll
            for (int j = 0; j < 4; j++) {
                float sx = sxA[j], sy = syA[j];
                float px = pxA[j], py = pyA[j];
                float a  = sx * sy;
                float xh = px + sx, yh = py + sy;
                int bx0 = (int)floorf(px / BS);
                int by0 = (int)floorf(py / BS);
                float blx0 = bx0 * BS, bly0 = by0 * BS;
                // node < bin size -> at most 2x2 bins; 3rd overlap exactly 0
                float ox0 = fmaxf(fminf(xh, blx0 + BS)       - fmaxf(px, blx0),      0.f);
                float ox1 = fmaxf(fminf(xh, blx0 + 2.f * BS) - fmaxf(px, blx0 + BS), 0.f);
                float oy0 = fmaxf(fminf(yh, bly0 + BS)       - fmaxf(py, bly0),      0.f);
                float oy1 = fmaxf(fminf(yh, bly0 + 2.f * BS) - fmaxf(py, bly0 + BS), 0.f);
                int bx1 = min(bx0 + 1, NB - 1);
                int by1 = min(by0 + 1, NB - 1);
                float2 m00 = __ldg(&g_maps[bx0 * NB + by0]);
                float2 m01 = __ldg(&g_maps[bx0 * NB + by1]);
                float2 m10 = __ldg(&g_maps[bx1 * NB + by0]);
                float2 m11 = __ldg(&g_maps[bx1 * NB + by1]);
                float w00 = ox0 * oy0, w01 = ox0 * oy1, w10 = ox1 * oy0, w11 = ox1 * oy1;
                float ro = w00 * m00.x + w01 * m01.x + w10 * m10.x + w11 * m11.x;
                float po = w00 * m00.y + w01 * m01.y + w10 * m10.y + w11 * m11.y;
                float ai = fmaxf(fmaxf(ro, po) - a, 0.f);
                inc[t][j] = ai;
                v_old += a;
                v_inc += ai;
                v_re  += fmaxf(ro - a, 0.f);
                v_pe  += fmaxf(po - a, 0.f);
            }
        } else {
            #pragma unroll
            for (int j = 0; j < 4; j++) v_f += sxA[j] * syA[j];
        }
    }
    // block reduce 5 accumulators
    #pragma unroll
    for (int off = 16; off; off >>= 1) {
        v_old += __shfl_down_sync(0xffffffffu, v_old, off);
        v_inc += __shfl_down_sync(0xffffffffu, v_inc, off);
        v_re  += __shfl_down_sync(0xffffffffu, v_re , off);
        v_pe  += __shfl_down_sync(0xffffffffu, v_pe , off);
        v_f   += __shfl_down_sync(0xffffffffu, v_f  , off);
    }
    __shared__ float sm[5][8];
    {
        int w = threadIdx.x >> 5, l = threadIdx.x & 31;
        if (l == 0) { sm[0][w] = v_old; sm[1][w] = v_inc; sm[2][w] = v_re; sm[3][w] = v_pe; sm[4][w] = v_f; }
    }
    __syncthreads();
    if (threadIdx.x == 0) {
        int bank = blockIdx.x & (NBANK - 1);
        #pragma unroll
        for (int j = 0; j < 5; j++) {
            float s = 0.f;
            #pragma unroll
            for (int k = 0; k < 8; k++) s += sm[j][k];
            atomicAdd(&g_acc[j][bank], (double)s);
        }
    }

    grid_bar(0u);   // all partial sums landed; sense back to initial value

    // ---------------- Phase 2: scalars (per block) + apply + write --------
    __shared__ float s_sc[4];   // 0:adjust 1:scale 2:fcond 3:fratio
    if (threadIdx.x < 32) {
        int l = threadIdx.x;
        double t0 = g_acc[0][l] + g_acc[0][l + 32];
        double t1 = g_acc[1][l] + g_acc[1][l + 32];
        double t2 = g_acc[2][l] + g_acc[2][l + 32];
        double t3 = g_acc[3][l] + g_acc[3][l + 32];
        double t4 = g_acc[4][l] + g_acc[4][l + 32];
        #pragma unroll
        for (int off = 16; off; off >>= 1) {
            t0 += __shfl_down_sync(0xffffffffu, t0, off);
            t1 += __shfl_down_sync(0xffffffffu, t1, off);
            t2 += __shfl_down_sync(0xffffffffu, t2, off);
            t3 += __shfl_down_sync(0xffffffffu, t3, off);
            t4 += __shfl_down_sync(0xffffffffu, t4, off);
        }
        if (l == 0) {
            float old_sum = (float)t0, inc_sum = (float)t1;
            float re = (float)t2, pe = (float)t3, fsum = (float)t4;
            float budget    = fminf(0.1f * 500000.0f, 1000000.0f - old_sum);
            float raw_scale = budget / inc_sum;
            float scale     = fminf(fmaxf(raw_scale, 0.f), 1.f);
            float inc_eff   = (raw_scale <= 0.f) ? 0.f : inc_sum * scale;
            float new_sum   = old_sum + inc_eff;
            bool route_flag = (re / old_sum) > 0.01f;
            bool pin_flag   = (pe / old_sum) > 0.05f;
            bool adjust = ((inc_eff / old_sum) > 0.01f) && (route_flag || pin_flag);
            bool fcond  = adjust && (new_sum + fsum > 1000000.0f);
            s_sc[0] = adjust ? 1.f : 0.f;
            s_sc[1] = scale;
            s_sc[2] = fcond ? 1.f : 0.f;
            s_sc[3] = sqrtf(fmaxf(1000000.0f - new_sum, 0.f) / fsum);
        }
    }
    __syncthreads();
    const float adjust = s_sc[0], scale = s_sc[1], fcond = s_sc[2], fratio = s_sc[3];

    #pragma unroll
    for (int t = 0; t < 2; t++) {
        int q = tid + t * NT;
        if (q >= NQ) break;
        float4 sx4 = nsx[q], sy4 = nsy[q], px4 = posx[q], py4 = posy[q];  // L1 hits
        float sxA[4], syA[4], pxA[4], pyA[4];
        *(float4*)sxA = sx4; *(float4*)syA = sy4;
        *(float4*)pxA = px4; *(float4*)pyA = py4;
        float nxA[4], nyA[4], qxA[4], qyA[4];
        if (q < NQ_MOV) {
            #pragma unroll
            for (int j = 0; j < 4; j++) {
                float sx = sxA[j], sy = syA[j];
                float nx = sx, ny = sy, qx = pxA[j], qy = pyA[j];
                if (adjust != 0.f) {
                    float a  = sx * sy;
                    float na = a + inc[t][j] * scale;
                    float mr = sqrtf(na / a);
                    nx = sx * mr; ny = sy * mr;
                    qx = pxA[j] + 0.5f * (sx - nx);
                    qy = pyA[j] + 0.5f * (sy - ny);
                }
                nxA[j] = nx; nyA[j] = ny; qxA[j] = qx; qyA[j] = qy;
            }
        } else {
            #pragma unroll
            for (int j = 0; j < 4; j++) {
                float sx = sxA[j], sy = syA[j];
                float nx = sx, ny = sy, qx = pxA[j], qy = pyA[j];
                if (fcond != 0.f) {
                    nx = sx * fratio; ny = sy * fratio;
                    qx = pxA[j] + 0.5f * (sx - nx);
                    qy = pyA[j] + 0.5f * (sy - ny);
                }
                nxA[j] = nx; nyA[j] = ny; qxA[j] = qx; qyA[j] = qy;
            }
        }
        out[q]          = *(const float4*)qxA;   // new pos x
        out[NQ + q]     = *(const float4*)qyA;   // new pos y
        out[2 * NQ + q] = *(const float4*)nxA;   // new node_size_x
        out[3 * NQ + q] = *(const float4*)nyA;   // new node_size_y
    }
}

// ----------------------------------------------------------------
extern "C" void kernel_launch(void* const* d_in, const int* in_sizes, int n_in,
                              void* d_out, int out_size) {
    const float* pos   = (const float*)d_in[0];
    const float* nsx   = (const float*)d_in[1];
    const float* nsy   = (const float*)d_in[2];
    const float* route = (const float*)d_in[6];
    const float* pin   = (const float*)d_in[7];

    k_fused<<<NBLK, NTHR>>>((const float4*)pos,
                            (const float4*)(pos + NUM_NODES),
                            (const float4*)nsx,
                            (const float4*)nsy,
                            (const float4*)route,
                            (const float4*)pin,
                            (float4*)d_out);
}